// round 4
// baseline (speedup 1.0000x reference)
#include <cuda_runtime.h>
#include <cuda_bf16.h>
#include <math.h>

#define B_SZ   16
#define C_IN   64
#define HH     256
#define WW     256
#define CKK    576
#define FC_DIM 512
#define IMG_PIX (HH * WW)
#define N_IMG  (B_SZ * C_IN)
#define FOUT_ELEMS ((size_t)N_IMG * IMG_PIX)

// Split-K partial buffers (deterministic: fixed summation order, no atomics)
__device__ float g_h_part[4][B_SZ * CKK];   // layer1 partials (kc0 includes b1)
__device__ float g_l_part[4][B_SZ * CKK];   // layer2 partials (kc0 includes b2)
__device__ float g_kw[B_SZ * CKK];          // softmaxed kernel weights

// ---------------------------------------------------------------------------
// Layer 1 partial: kc-th 128-slice of h = Fc@W1 (+b1 on kc==0).
// grid (3, 64): x = j-chunk (192 wide), y = b*4 + kc. 192 threads.
// ---------------------------------------------------------------------------
__global__ __launch_bounds__(192) void EKG_mlp1_part(
    const float* __restrict__ Fc,
    const float* __restrict__ W1, const float* __restrict__ b1)
{
    __shared__ float sin_[128];
    const int b  = blockIdx.y >> 2;
    const int kc = blockIdx.y & 3;
    const int j  = blockIdx.x * 192 + threadIdx.x;
    const int i0 = kc * 128;

    if (threadIdx.x < 128) sin_[threadIdx.x] = Fc[b * FC_DIM + i0 + threadIdx.x];
    __syncthreads();

    float a0 = 0.f, a1 = 0.f, a2 = 0.f, a3 = 0.f;
    const float* __restrict__ wp = W1 + (size_t)i0 * CKK + j;
    #pragma unroll
    for (int i = 0; i < 128; i += 4) {
        a0 = fmaf(sin_[i + 0], wp[(i + 0) * CKK], a0);
        a1 = fmaf(sin_[i + 1], wp[(i + 1) * CKK], a1);
        a2 = fmaf(sin_[i + 2], wp[(i + 2) * CKK], a2);
        a3 = fmaf(sin_[i + 3], wp[(i + 3) * CKK], a3);
    }
    float acc = (a0 + a1) + (a2 + a3);
    if (kc == 0) acc += b1[j];
    g_h_part[kc][b * CKK + j] = acc;
}

// ---------------------------------------------------------------------------
// Layer 2 partial: kc-th 144-slice of logits = relu(h)@W2 (+b2 on kc==0).
// grid (3, 64), 192 threads.
// ---------------------------------------------------------------------------
__global__ __launch_bounds__(192) void EKG_mlp2_part(
    const float* __restrict__ W2, const float* __restrict__ b2)
{
    __shared__ float sh[144];
    const int b  = blockIdx.y >> 2;
    const int kc = blockIdx.y & 3;
    const int j  = blockIdx.x * 192 + threadIdx.x;
    const int i0 = kc * 144;

    if (threadIdx.x < 144) {
        const int idx = b * CKK + i0 + threadIdx.x;
        float h = ((g_h_part[0][idx] + g_h_part[1][idx]) +
                   (g_h_part[2][idx] + g_h_part[3][idx]));
        sh[threadIdx.x] = fmaxf(h, 0.0f);
    }
    __syncthreads();

    float a0 = 0.f, a1 = 0.f, a2 = 0.f, a3 = 0.f;
    const float* __restrict__ wp = W2 + (size_t)i0 * CKK + j;
    #pragma unroll
    for (int i = 0; i < 144; i += 4) {
        a0 = fmaf(sh[i + 0], wp[(i + 0) * CKK], a0);
        a1 = fmaf(sh[i + 1], wp[(i + 1) * CKK], a1);
        a2 = fmaf(sh[i + 2], wp[(i + 2) * CKK], a2);
        a3 = fmaf(sh[i + 3], wp[(i + 3) * CKK], a3);
    }
    float acc = (a0 + a1) + (a2 + a3);
    if (kc == 0) acc += b2[j];
    g_l_part[kc][b * CKK + j] = acc;
}

// ---------------------------------------------------------------------------
// Softmax over 576 (summing the 4 logit partials). grid 16, block 576.
// ---------------------------------------------------------------------------
__global__ __launch_bounds__(CKK) void EKG_softmax(
    float* __restrict__ kw_tail, int write_tail)
{
    __shared__ float red[32];
    __shared__ float bcast;
    const int b = blockIdx.x;
    const int j = threadIdx.x;
    const int lane = j & 31;
    const int wid  = j >> 5;
    const int idx  = b * CKK + j;

    const float logit = ((g_l_part[0][idx] + g_l_part[1][idx]) +
                         (g_l_part[2][idx] + g_l_part[3][idx]));

    float m = logit;
    #pragma unroll
    for (int o = 16; o > 0; o >>= 1)
        m = fmaxf(m, __shfl_xor_sync(0xffffffffu, m, o));
    if (lane == 0) red[wid] = m;
    __syncthreads();
    if (wid == 0) {
        float v = (lane < 18) ? red[lane] : -INFINITY;
        #pragma unroll
        for (int o = 16; o > 0; o >>= 1)
            v = fmaxf(v, __shfl_xor_sync(0xffffffffu, v, o));
        if (lane == 0) bcast = v;
    }
    __syncthreads();
    const float e = expf(logit - bcast);

    float s = e;
    #pragma unroll
    for (int o = 16; o > 0; o >>= 1)
        s += __shfl_xor_sync(0xffffffffu, s, o);
    __syncthreads();
    if (lane == 0) red[wid] = s;
    __syncthreads();
    if (wid == 0) {
        float v = (lane < 18) ? red[lane] : 0.0f;
        #pragma unroll
        for (int o = 16; o > 0; o >>= 1)
            v += __shfl_xor_sync(0xffffffffu, v, o);
        if (lane == 0) bcast = v;
    }
    __syncthreads();

    const float kw = e / bcast;
    g_kw[idx] = kw;
    if (write_tail) kw_tail[idx] = kw;
}

// ---------------------------------------------------------------------------
// Depthwise 3x3 conv, reflect pad, no smem, register row rotation.
// Block 256: tx 0..63 (col group, float4), ty 0..3 (strip of 32 rows).
// Block tile: 256 cols x 128 rows. Grid (2, 1024).
// ---------------------------------------------------------------------------
#define ROWS_PER_BLOCK 128
#define ROWS_PER_THREAD 32

__device__ __forceinline__ void load_row6(
    const float* __restrict__ img, int gr, int tx, float* __restrict__ w)
{
    gr = (gr < 0) ? 1 : ((gr > HH - 1) ? (2 * HH - 2 - gr) : gr);
    const float* rowp = img + gr * WW;
    const float4 q = __ldg((const float4*)rowp + tx);
    w[1] = q.x; w[2] = q.y; w[3] = q.z; w[4] = q.w;
    w[0] = (tx == 0)      ? q.y : __ldg(rowp + 4 * tx - 1);
    w[5] = (tx == WW/4-1) ? q.z : __ldg(rowp + 4 * tx + 4);
}

__global__ __launch_bounds__(256) void EKG_conv_kernel(
    const float* __restrict__ Fd,
    float* __restrict__ out)
{
    const int bc   = blockIdx.y;
    const int tid  = threadIdx.x;
    const int tx   = tid & 63;
    const int ty   = tid >> 6;
    const int rbase = blockIdx.x * ROWS_PER_BLOCK + ty * ROWS_PER_THREAD;

    const float* __restrict__ img = Fd  + (size_t)bc * IMG_PIX;
    float*       __restrict__ o   = out + (size_t)bc * IMG_PIX;

    const float* kwp = g_kw + bc * 9;
    const float w00 = __ldg(kwp+0), w01 = __ldg(kwp+1), w02 = __ldg(kwp+2);
    const float w10 = __ldg(kwp+3), w11 = __ldg(kwp+4), w12 = __ldg(kwp+5);
    const float w20 = __ldg(kwp+6), w21 = __ldg(kwp+7), w22 = __ldg(kwp+8);

    float win[3][6];
    load_row6(img, rbase - 1, tx, win[0]);
    load_row6(img, rbase + 0, tx, win[1]);

    #pragma unroll 8
    for (int rr = 0; rr < ROWS_PER_THREAD; ++rr) {
        load_row6(img, rbase + rr + 1, tx, win[(rr + 2) % 3]);

        const float* T  = win[rr % 3];
        const float* M  = win[(rr + 1) % 3];
        const float* Bt = win[(rr + 2) % 3];

        float4 r;
        r.x = w00*T[0]; r.x = fmaf(w01,T[1],r.x); r.x = fmaf(w02,T[2],r.x);
        r.x = fmaf(w10,M[0],r.x); r.x = fmaf(w11,M[1],r.x); r.x = fmaf(w12,M[2],r.x);
        r.x = fmaf(w20,Bt[0],r.x); r.x = fmaf(w21,Bt[1],r.x); r.x = fmaf(w22,Bt[2],r.x);

        r.y = w00*T[1]; r.y = fmaf(w01,T[2],r.y); r.y = fmaf(w02,T[3],r.y);
        r.y = fmaf(w10,M[1],r.y); r.y = fmaf(w11,M[2],r.y); r.y = fmaf(w12,M[3],r.y);
        r.y = fmaf(w20,Bt[1],r.y); r.y = fmaf(w21,Bt[2],r.y); r.y = fmaf(w22,Bt[3],r.y);

        r.z = w00*T[2]; r.z = fmaf(w01,T[3],r.z); r.z = fmaf(w02,T[4],r.z);
        r.z = fmaf(w10,M[2],r.z); r.z = fmaf(w11,M[3],r.z); r.z = fmaf(w12,M[4],r.z);
        r.z = fmaf(w20,Bt[2],r.z); r.z = fmaf(w21,Bt[3],r.z); r.z = fmaf(w22,Bt[4],r.z);

        r.w = w00*T[3]; r.w = fmaf(w01,T[4],r.w); r.w = fmaf(w02,T[5],r.w);
        r.w = fmaf(w10,M[3],r.w); r.w = fmaf(w11,M[4],r.w); r.w = fmaf(w12,M[5],r.w);
        r.w = fmaf(w20,Bt[3],r.w); r.w = fmaf(w21,Bt[4],r.w); r.w = fmaf(w22,Bt[5],r.w);

        __stcs((float4*)(o + (size_t)(rbase + rr) * WW + 4 * tx), r);
    }
}

// ---------------------------------------------------------------------------
extern "C" void kernel_launch(void* const* d_in, const int* in_sizes, int n_in,
                              void* d_out, int out_size) {
    const float* Fd = (const float*)d_in[0];
    const float* Fc = (const float*)d_in[1];
    const float* W1 = (const float*)d_in[2];
    const float* b1 = (const float*)d_in[3];
    const float* W2 = (const float*)d_in[4];
    const float* b2 = (const float*)d_in[5];
    float* out = (float*)d_out;

    const int write_tail = ((size_t)out_size >= FOUT_ELEMS + (size_t)B_SZ * CKK) ? 1 : 0;
    float* kw_tail = out + FOUT_ELEMS;

    EKG_mlp1_part<<<dim3(3, B_SZ * 4), 192>>>(Fc, W1, b1);
    EKG_mlp2_part<<<dim3(3, B_SZ * 4), 192>>>(W2, b2);
    EKG_softmax<<<B_SZ, CKK>>>(kw_tail, write_tail);

    dim3 grid(HH / ROWS_PER_BLOCK, N_IMG);
    EKG_conv_kernel<<<grid, 256>>>(Fd, out);
}

// round 5
// speedup vs baseline: 1.4710x; 1.4710x over previous
#include <cuda_runtime.h>
#include <cuda_bf16.h>
#include <math.h>

#define B_SZ   16
#define C_IN   64
#define HH     256
#define WW     256
#define CKK    576
#define FC_DIM 512
#define IMG_PIX (HH * WW)
#define N_IMG  (B_SZ * C_IN)
#define FOUT_ELEMS ((size_t)N_IMG * IMG_PIX)

// Split-K partial buffers (deterministic: fixed summation order, no atomics)
__device__ float g_h_part[4][B_SZ * CKK];
__device__ float g_l_part[4][B_SZ * CKK];
__device__ float g_kw[B_SZ * CKK];

// ---------------------------------------------------------------------------
// Layer 1 partial: kc-th 128-slice of h = Fc@W1 (+b1 on kc==0).
// grid (3, 64), 192 threads.
// ---------------------------------------------------------------------------
__global__ __launch_bounds__(192) void EKG_mlp1_part(
    const float* __restrict__ Fc,
    const float* __restrict__ W1, const float* __restrict__ b1)
{
    __shared__ float sin_[128];
    const int b  = blockIdx.y >> 2;
    const int kc = blockIdx.y & 3;
    const int j  = blockIdx.x * 192 + threadIdx.x;
    const int i0 = kc * 128;

    if (threadIdx.x < 128) sin_[threadIdx.x] = Fc[b * FC_DIM + i0 + threadIdx.x];
    __syncthreads();

    float a0 = 0.f, a1 = 0.f, a2 = 0.f, a3 = 0.f;
    const float* __restrict__ wp = W1 + (size_t)i0 * CKK + j;
    #pragma unroll
    for (int i = 0; i < 128; i += 4) {
        a0 = fmaf(sin_[i + 0], wp[(i + 0) * CKK], a0);
        a1 = fmaf(sin_[i + 1], wp[(i + 1) * CKK], a1);
        a2 = fmaf(sin_[i + 2], wp[(i + 2) * CKK], a2);
        a3 = fmaf(sin_[i + 3], wp[(i + 3) * CKK], a3);
    }
    float acc = (a0 + a1) + (a2 + a3);
    if (kc == 0) acc += b1[j];
    g_h_part[kc][b * CKK + j] = acc;
}

// ---------------------------------------------------------------------------
// Layer 2 partial: kc-th 144-slice of logits = relu(h)@W2 (+b2 on kc==0).
// grid (3, 64), 192 threads.
// ---------------------------------------------------------------------------
__global__ __launch_bounds__(192) void EKG_mlp2_part(
    const float* __restrict__ W2, const float* __restrict__ b2)
{
    __shared__ float sh[144];
    const int b  = blockIdx.y >> 2;
    const int kc = blockIdx.y & 3;
    const int j  = blockIdx.x * 192 + threadIdx.x;
    const int i0 = kc * 144;

    if (threadIdx.x < 144) {
        const int idx = b * CKK + i0 + threadIdx.x;
        float h = ((g_h_part[0][idx] + g_h_part[1][idx]) +
                   (g_h_part[2][idx] + g_h_part[3][idx]));
        sh[threadIdx.x] = fmaxf(h, 0.0f);
    }
    __syncthreads();

    float a0 = 0.f, a1 = 0.f, a2 = 0.f, a3 = 0.f;
    const float* __restrict__ wp = W2 + (size_t)i0 * CKK + j;
    #pragma unroll
    for (int i = 0; i < 144; i += 4) {
        a0 = fmaf(sh[i + 0], wp[(i + 0) * CKK], a0);
        a1 = fmaf(sh[i + 1], wp[(i + 1) * CKK], a1);
        a2 = fmaf(sh[i + 2], wp[(i + 2) * CKK], a2);
        a3 = fmaf(sh[i + 3], wp[(i + 3) * CKK], a3);
    }
    float acc = (a0 + a1) + (a2 + a3);
    if (kc == 0) acc += b2[j];
    g_l_part[kc][b * CKK + j] = acc;
}

// ---------------------------------------------------------------------------
// Softmax over 576 (summing the 4 logit partials). grid 16, block 576.
// ---------------------------------------------------------------------------
__global__ __launch_bounds__(CKK) void EKG_softmax(
    float* __restrict__ kw_tail, int write_tail)
{
    __shared__ float red[32];
    __shared__ float bcast;
    const int b = blockIdx.x;
    const int j = threadIdx.x;
    const int lane = j & 31;
    const int wid  = j >> 5;
    const int idx  = b * CKK + j;

    const float logit = ((g_l_part[0][idx] + g_l_part[1][idx]) +
                         (g_l_part[2][idx] + g_l_part[3][idx]));

    float m = logit;
    #pragma unroll
    for (int o = 16; o > 0; o >>= 1)
        m = fmaxf(m, __shfl_xor_sync(0xffffffffu, m, o));
    if (lane == 0) red[wid] = m;
    __syncthreads();
    if (wid == 0) {
        float v = (lane < 18) ? red[lane] : -INFINITY;
        #pragma unroll
        for (int o = 16; o > 0; o >>= 1)
            v = fmaxf(v, __shfl_xor_sync(0xffffffffu, v, o));
        if (lane == 0) bcast = v;
    }
    __syncthreads();
    const float e = expf(logit - bcast);

    float s = e;
    #pragma unroll
    for (int o = 16; o > 0; o >>= 1)
        s += __shfl_xor_sync(0xffffffffu, s, o);
    __syncthreads();
    if (lane == 0) red[wid] = s;
    __syncthreads();
    if (wid == 0) {
        float v = (lane < 18) ? red[lane] : 0.0f;
        #pragma unroll
        for (int o = 16; o > 0; o >>= 1)
            v += __shfl_xor_sync(0xffffffffu, v, o);
        if (lane == 0) bcast = v;
    }
    __syncthreads();

    const float kw = e / bcast;
    g_kw[idx] = kw;
    if (write_tail) kw_tail[idx] = kw;
}

// ---------------------------------------------------------------------------
// Depthwise 3x3 conv, reflect pad, no smem (Round-3 measured-best config).
// Block 256: tx 0..63 (float4 col group), ty 0..3 (strip of 8 rows).
// Block tile: 256 x 32. Grid (8, 1024).
// ---------------------------------------------------------------------------
#define ROWS_PER_BLOCK 32
#define ROWS_PER_THREAD 8

__device__ __forceinline__ void load_row6(
    const float* __restrict__ img, int gr, int tx, float* __restrict__ w)
{
    gr = (gr < 0) ? 1 : ((gr > HH - 1) ? (2 * HH - 2 - gr) : gr);
    const float* rowp = img + gr * WW;
    const float4 q = __ldg((const float4*)rowp + tx);
    w[1] = q.x; w[2] = q.y; w[3] = q.z; w[4] = q.w;
    w[0] = (tx == 0)      ? q.y : __ldg(rowp + 4 * tx - 1);
    w[5] = (tx == WW/4-1) ? q.z : __ldg(rowp + 4 * tx + 4);
}

__global__ __launch_bounds__(256) void EKG_conv_kernel(
    const float* __restrict__ Fd,
    float* __restrict__ out)
{
    const int bc   = blockIdx.y;
    const int tid  = threadIdx.x;
    const int tx   = tid & 63;
    const int ty   = tid >> 6;
    const int rbase = blockIdx.x * ROWS_PER_BLOCK + ty * ROWS_PER_THREAD;

    const float* __restrict__ img = Fd  + (size_t)bc * IMG_PIX;
    float*       __restrict__ o   = out + (size_t)bc * IMG_PIX;

    const float* kwp = g_kw + bc * 9;
    const float w00 = __ldg(kwp+0), w01 = __ldg(kwp+1), w02 = __ldg(kwp+2);
    const float w10 = __ldg(kwp+3), w11 = __ldg(kwp+4), w12 = __ldg(kwp+5);
    const float w20 = __ldg(kwp+6), w21 = __ldg(kwp+7), w22 = __ldg(kwp+8);

    float win[3][6];
    load_row6(img, rbase - 1, tx, win[0]);
    load_row6(img, rbase + 0, tx, win[1]);

    #pragma unroll
    for (int rr = 0; rr < ROWS_PER_THREAD; ++rr) {
        load_row6(img, rbase + rr + 1, tx, win[(rr + 2) % 3]);

        const float* T  = win[rr % 3];
        const float* M  = win[(rr + 1) % 3];
        const float* Bt = win[(rr + 2) % 3];

        float4 r;
        r.x = w00*T[0]; r.x = fmaf(w01,T[1],r.x); r.x = fmaf(w02,T[2],r.x);
        r.x = fmaf(w10,M[0],r.x); r.x = fmaf(w11,M[1],r.x); r.x = fmaf(w12,M[2],r.x);
        r.x = fmaf(w20,Bt[0],r.x); r.x = fmaf(w21,Bt[1],r.x); r.x = fmaf(w22,Bt[2],r.x);

        r.y = w00*T[1]; r.y = fmaf(w01,T[2],r.y); r.y = fmaf(w02,T[3],r.y);
        r.y = fmaf(w10,M[1],r.y); r.y = fmaf(w11,M[2],r.y); r.y = fmaf(w12,M[3],r.y);
        r.y = fmaf(w20,Bt[1],r.y); r.y = fmaf(w21,Bt[2],r.y); r.y = fmaf(w22,Bt[3],r.y);

        r.z = w00*T[2]; r.z = fmaf(w01,T[3],r.z); r.z = fmaf(w02,T[4],r.z);
        r.z = fmaf(w10,M[2],r.z); r.z = fmaf(w11,M[3],r.z); r.z = fmaf(w12,M[4],r.z);
        r.z = fmaf(w20,Bt[2],r.z); r.z = fmaf(w21,Bt[3],r.z); r.z = fmaf(w22,Bt[4],r.z);

        r.w = w00*T[3]; r.w = fmaf(w01,T[4],r.w); r.w = fmaf(w02,T[5],r.w);
        r.w = fmaf(w10,M[3],r.w); r.w = fmaf(w11,M[4],r.w); r.w = fmaf(w12,M[5],r.w);
        r.w = fmaf(w20,Bt[3],r.w); r.w = fmaf(w21,Bt[4],r.w); r.w = fmaf(w22,Bt[5],r.w);

        __stcs((float4*)(o + (size_t)(rbase + rr) * WW + 4 * tx), r);
    }
}

// ---------------------------------------------------------------------------
extern "C" void kernel_launch(void* const* d_in, const int* in_sizes, int n_in,
                              void* d_out, int out_size) {
    const float* Fd = (const float*)d_in[0];
    const float* Fc = (const float*)d_in[1];
    const float* W1 = (const float*)d_in[2];
    const float* b1 = (const float*)d_in[3];
    const float* W2 = (const float*)d_in[4];
    const float* b2 = (const float*)d_in[5];
    float* out = (float*)d_out;

    const int write_tail = ((size_t)out_size >= FOUT_ELEMS + (size_t)B_SZ * CKK) ? 1 : 0;
    float* kw_tail = out + FOUT_ELEMS;

    EKG_mlp1_part<<<dim3(3, B_SZ * 4), 192>>>(Fc, W1, b1);
    EKG_mlp2_part<<<dim3(3, B_SZ * 4), 192>>>(W2, b2);
    EKG_softmax<<<B_SZ, CKK>>>(kw_tail, write_tail);

    dim3 grid(HH / ROWS_PER_BLOCK, N_IMG);
    EKG_conv_kernel<<<grid, 256>>>(Fd, out);
}